// round 7
// baseline (speedup 1.0000x reference)
#include <cuda_runtime.h>
#include <cuda_bf16.h>
#include <math.h>

// ---------------------------------------------------------------------------
// NCA_3D  (B=8, C=16, S=64, HID=32, fp32)
// R7: R6 HMMA pipeline +
//   - channel-invariant slab offsets hoisted to registers (kills ~1600 ALU/thr)
//   - rmask prefetched at kernel start into a 16-bit mask (floor(rm+.25)==rm>=.75)
//   - Sobel channel loop unrolled x2
// ---------------------------------------------------------------------------

typedef unsigned int u32;

__device__ u32  g_w1t[32 * 64 / 2];    // bf16 [n=32][k=64], k = 4c+seg
__device__ u32  g_w2t[16 * 32 / 2];    // bf16 [n=16][k=32]  (= W2 verbatim)
__device__ float g_alpha[8u << 18];

__device__ __forceinline__ u32 cvt_bf16x2(float hi, float lo) {
    u32 r; asm("cvt.rn.bf16x2.f32 %0, %1, %2;" : "=r"(r) : "f"(hi), "f"(lo)); return r;
}
__device__ __forceinline__ void mma16816(float* d, const u32* a, const u32* b) {
    asm("mma.sync.aligned.m16n8k16.row.col.f32.bf16.bf16.f32 "
        "{%0,%1,%2,%3}, {%4,%5,%6,%7}, {%8,%9}, {%0,%1,%2,%3};"
        : "+f"(d[0]), "+f"(d[1]), "+f"(d[2]), "+f"(d[3])
        : "r"(a[0]), "r"(a[1]), "r"(a[2]), "r"(a[3]), "r"(b[0]), "r"(b[1]));
}

#define S_SLAB 360            // 6d x 6h x 10w per channel
#define A_PITCH_U32 36        // 144 B row pitch
// smem byte offsets
#define OFF_SLAB 0
#define OFF_A    23040        // 128 * 144 = 18432
#define OFF_W1   41472        // 4096
#define OFF_W2   45568        // 1024
#define OFF_BIAS 46592        // 128
#define SMEM_P1  46720

// ---------------------------------------------------------------------------
__global__ void nca_prep(const float* __restrict__ W1, const float* __restrict__ W2)
{
    int t = threadIdx.x;
    __nv_bfloat16* w1 = (__nv_bfloat16*)g_w1t;
    for (int i = t; i < 32 * 64; i += 256) {
        int n = i >> 6, k = i & 63;
        w1[i] = __float2bfloat16(W1[n * 64 + (k & 3) * 16 + (k >> 2)]);
    }
    __nv_bfloat16* w2 = (__nv_bfloat16*)g_w2t;
    for (int i = t; i < 16 * 32; i += 256)
        w2[i] = __float2bfloat16(W2[i]);
}

// spatial offset for slab index r (6d x 6h x 10w halo), wrapped
__device__ __forceinline__ u32 slab_off(int r, int d0, int h0, int w0) {
    int sd = r / 60; int rem = r - sd * 60;
    int sh = rem / 10; int sw = rem - sh * 10;
    int gd = (d0 + sd - 1) & 63;
    int gh = (h0 + sh - 1) & 63;
    int gw = (w0 + sw - 1) & 63;
    return ((u32)gd << 12) + ((u32)gh << 6) + (u32)gw;
}

// ---------------------------------------------------------------------------
__global__ __launch_bounds__(128, 4)
void nca_pass1(const float* __restrict__ x, const float* __restrict__ rmask,
               const float* __restrict__ b1, float* __restrict__ out)
{
    extern __shared__ char smraw[];
    float* slab = (float*)(smraw + OFF_SLAB);
    u32*   Au   = (u32*)(smraw + OFF_A);
    u32*   w1u  = (u32*)(smraw + OFF_W1);
    u32*   w2u  = (u32*)(smraw + OFF_W2);
    float* sB   = (float*)(smraw + OFF_BIAS);

    int tid  = threadIdx.x;
    int warp = tid >> 5;
    int lane = tid & 31;
    int g = lane >> 2, c = lane & 3;

    int blk = blockIdx.x;
    int w0 = (blk & 7) << 3;
    int h0 = ((blk >> 3) & 15) << 2;
    int d0 = ((blk >> 7) & 15) << 2;
    int b  = blk >> 11;
    const size_t baseB = (size_t)b << 22;

    // ---- rmask prefetch -> 16-bit update mask (floor(rm+0.25) == rm>=0.75) ----
    u32 um = 0;
    {
        float rv[16];
        int d = d0 + warp, ww = w0 + g;
        size_t vb = baseB + ((size_t)d << 12) + ww;
#pragma unroll
        for (int mt = 0; mt < 2; mt++)
#pragma unroll
            for (int h2 = 0; h2 < 2; h2++) {
                int hh = h0 + mt * 2 + h2;
                size_t sp = vb + ((size_t)hh << 6);
#pragma unroll
                for (int nt = 0; nt < 2; nt++)
#pragma unroll
                    for (int lh = 0; lh < 2; lh++) {
                        int ch = 2 * c + lh + 8 * nt;
                        rv[(mt * 2 + h2) * 4 + nt * 2 + lh] = rmask[sp + ((size_t)ch << 18)];
                    }
            }
#pragma unroll
        for (int i = 0; i < 16; i++)
            um |= (rv[i] >= 0.75f) ? (1u << i) : 0u;
    }

    // ---- channel-invariant slab offsets (3 per thread) ----
    u32 o0 = slab_off(tid, d0, h0, w0);
    u32 o1 = slab_off(tid + 128, d0, h0, w0);
    u32 o2 = (tid < S_SLAB - 256) ? slab_off(tid + 256, d0, h0, w0) : 0u;

    // ---- stage x slab (reuse offsets across channels) ----
    {
        const float* xb = x + baseB;
#pragma unroll 1
        for (int ch = 0; ch < 16; ch++) {
            const float* xc = xb + ((size_t)ch << 18);
            float* sc = slab + ch * S_SLAB;
            sc[tid]       = xc[o0];
            sc[tid + 128] = xc[o1];
            if (tid < S_SLAB - 256) sc[tid + 256] = xc[o2];
        }
    }
    // ---- stage weights + bias ----
    {
        uint4* d1 = (uint4*)w1u; const uint4* s1 = (const uint4*)g_w1t;
        for (int i = tid; i < 256; i += 128) d1[i] = s1[i];
        uint4* d2 = (uint4*)w2u; const uint4* s2 = (const uint4*)g_w2t;
        if (tid < 64) d2[tid] = s2[tid];
        if (tid < 32) sB[tid] = b1[tid];
    }
    __syncthreads();

    // ---- Sobel -> bf16 A rows (row = tid, k = 4c+seg) ----
    {
        int vw = tid & 7, vh = (tid >> 3) & 3, vd = tid >> 5;
        uint2* Arow = (uint2*)((char*)Au + tid * 144);
#pragma unroll 2
        for (int ch = 0; ch < 16; ch++) {
            const float* s = slab + ch * S_SLAB + vd * 60 + vh * 10 + vw;
            float v[27];
#pragma unroll
            for (int i = 0; i < 3; i++)
#pragma unroll
                for (int j = 0; j < 3; j++)
#pragma unroll
                    for (int k = 0; k < 3; k++)
                        v[(i * 3 + j) * 3 + k] = s[i * 60 + j * 10 + k];

            float a[9];
#pragma unroll
            for (int j = 0; j < 3; j++)
#pragma unroll
                for (int k = 0; k < 3; k++)
                    a[j * 3 + k] = fmaf(2.f, v[9 + j * 3 + k], v[j * 3 + k] + v[18 + j * 3 + k]);

            float gx = fmaf(2.f, a[5] - a[3], (a[2] - a[0]) + (a[8] - a[6]));
            float gy = fmaf(2.f, a[7] - a[1], (a[6] - a[0]) + (a[8] - a[2]));
            float r0 = fmaf(2.f, v[19] - v[1], (v[18] - v[0]) + (v[20] - v[2]));
            float r1 = fmaf(2.f, v[22] - v[4], (v[21] - v[3]) + (v[23] - v[5]));
            float r2 = fmaf(2.f, v[25] - v[7], (v[24] - v[6]) + (v[26] - v[8]));
            float gz = fmaf(2.f, r1, r0 + r2);
            float xc = v[13];

            uint2 pk;
            pk.x = cvt_bf16x2(gy, gx);   // k=4c, 4c+1
            pk.y = cvt_bf16x2(xc, gz);   // k=4c+2, 4c+3
            Arow[ch] = pk;
        }
    }
    __syncthreads();

    // ---- B fragments (one-time) ----
    u32 B1f[4][4][2];   // [nt][kt]
#pragma unroll
    for (int nt = 0; nt < 4; nt++)
#pragma unroll
        for (int kt = 0; kt < 4; kt++) {
            int idx = (g + 8 * nt) * 32 + 8 * kt + c;
            B1f[nt][kt][0] = w1u[idx];
            B1f[nt][kt][1] = w1u[idx + 4];
        }
    u32 B2f[2][2][2];   // [nt2][kt2]
#pragma unroll
    for (int nt = 0; nt < 2; nt++)
#pragma unroll
        for (int kt = 0; kt < 2; kt++) {
            int idx = (g + 8 * nt) * 16 + 8 * kt + c;
            B2f[nt][kt][0] = w2u[idx];
            B2f[nt][kt][1] = w2u[idx + 4];
        }

    // ---- GEMM1: M32 N32 K64 ----
    float C1[2][4][4];
#pragma unroll
    for (int mt = 0; mt < 2; mt++)
#pragma unroll
        for (int nt = 0; nt < 4; nt++)
#pragma unroll
            for (int q = 0; q < 4; q++) C1[mt][nt][q] = 0.f;

#pragma unroll
    for (int kt = 0; kt < 4; kt++) {
#pragma unroll
        for (int mt = 0; mt < 2; mt++) {
            int r = warp * 32 + mt * 16 + g;
            int base = r * A_PITCH_U32 + 8 * kt + c;
            u32 a[4];
            a[0] = Au[base];
            a[1] = Au[base + 8 * A_PITCH_U32];
            a[2] = Au[base + 4];
            a[3] = Au[base + 8 * A_PITCH_U32 + 4];
#pragma unroll
            for (int nt = 0; nt < 4; nt++)
                mma16816(C1[mt][nt], a, B1f[nt][kt]);
        }
    }

    // ---- bias + relu ----
#pragma unroll
    for (int nt = 0; nt < 4; nt++) {
        float blo = sB[2 * c + 8 * nt];
        float bhi = sB[2 * c + 1 + 8 * nt];
#pragma unroll
        for (int mt = 0; mt < 2; mt++) {
            C1[mt][nt][0] = fmaxf(C1[mt][nt][0] + blo, 0.f);
            C1[mt][nt][1] = fmaxf(C1[mt][nt][1] + bhi, 0.f);
            C1[mt][nt][2] = fmaxf(C1[mt][nt][2] + blo, 0.f);
            C1[mt][nt][3] = fmaxf(C1[mt][nt][3] + bhi, 0.f);
        }
    }

    // ---- repack C1 frags -> A2 frags (registers only) ----
    u32 A2f[2][2][4];   // [mt][kt2]
#pragma unroll
    for (int mt = 0; mt < 2; mt++)
#pragma unroll
        for (int kt = 0; kt < 2; kt++) {
            A2f[mt][kt][0] = cvt_bf16x2(C1[mt][2 * kt][1],     C1[mt][2 * kt][0]);
            A2f[mt][kt][1] = cvt_bf16x2(C1[mt][2 * kt][3],     C1[mt][2 * kt][2]);
            A2f[mt][kt][2] = cvt_bf16x2(C1[mt][2 * kt + 1][1], C1[mt][2 * kt + 1][0]);
            A2f[mt][kt][3] = cvt_bf16x2(C1[mt][2 * kt + 1][3], C1[mt][2 * kt + 1][2]);
        }

    // ---- GEMM2: M32 N16 K32 ----
    float D2[2][2][4];
#pragma unroll
    for (int mt = 0; mt < 2; mt++)
#pragma unroll
        for (int nt = 0; nt < 2; nt++)
#pragma unroll
            for (int q = 0; q < 4; q++) D2[mt][nt][q] = 0.f;
#pragma unroll
    for (int kt = 0; kt < 2; kt++)
#pragma unroll
        for (int mt = 0; mt < 2; mt++)
#pragma unroll
            for (int nt = 0; nt < 2; nt++)
                mma16816(D2[mt][nt], A2f[mt][kt], B2f[nt][kt]);

    // ---- epilogue (rmask bits from um) ----
    {
        int vw = g, vd = warp;
        int d = d0 + vd, ww = w0 + vw;
#pragma unroll
        for (int mt = 0; mt < 2; mt++)
#pragma unroll
            for (int h2 = 0; h2 < 2; h2++) {
                int vh = mt * 2 + h2;
                int hh = h0 + vh;
                size_t sp = ((size_t)d << 12) + (hh << 6) + ww;
                int sctr = (vd + 1) * 60 + (vh + 1) * 10 + (vw + 1);
#pragma unroll
                for (int nt = 0; nt < 2; nt++)
#pragma unroll
                    for (int lh = 0; lh < 2; lh++) {
                        int ch = 2 * c + lh + 8 * nt;
                        int bi = (mt * 2 + h2) * 4 + nt * 2 + lh;
                        float dy = D2[mt][nt][h2 * 2 + lh];
                        float xv = slab[ch * S_SLAB + sctr];
                        float add = (um >> bi) & 1 ? dy : 0.f;
                        float y = xv + add;
                        out[baseB + ((size_t)ch << 18) + sp] = y;
                        if (ch == 3) g_alpha[((size_t)b << 18) + sp] = y;
                    }
            }
    }
}

// ---------------------------------------------------------------------------
__global__ __launch_bounds__(256)
void nca_pass2(float* __restrict__ out)
{
    __shared__ float sa[600];

    int blk = blockIdx.x;
    int w0 = (blk & 7) << 3;
    int h0 = ((blk >> 3) & 7) << 3;
    int d0 = ((blk >> 6) & 15) << 2;
    int b  = blk >> 10;
    int tid = threadIdx.x;

    const float* ap = g_alpha + ((size_t)b << 18);
    for (int i = tid; i < 600; i += 256) {
        int dd = i / 100; int r = i - dd * 100;
        int hh = r / 10;  int ww = r - hh * 10;
        int gd = d0 + dd - 1, gh = h0 + hh - 1, gw = w0 + ww - 1;
        float val = -3.4e38f;
        if ((unsigned)gd < 64u && (unsigned)gh < 64u && (unsigned)gw < 64u)
            val = ap[((size_t)gd << 12) + (gh << 6) + gw];
        sa[i] = val;
    }
    __syncthreads();

    int wx = tid & 7, hy = (tid >> 3) & 7, dz = tid >> 6;
    const float* s = sa + dz * 100 + hy * 10 + wx;
    float m = -3.4e38f;
#pragma unroll
    for (int i = 0; i < 3; i++)
#pragma unroll
        for (int j = 0; j < 3; j++)
#pragma unroll
            for (int k = 0; k < 3; k++)
                m = fmaxf(m, s[i * 100 + j * 10 + k]);

    if (!(m > 0.1f)) {
        size_t sp = ((size_t)b << 22) + ((size_t)(d0 + dz) << 12) + ((h0 + hy) << 6) + (w0 + wx);
#pragma unroll
        for (int c = 0; c < 16; c++)
            out[sp + ((size_t)c << 18)] = 0.f;
    }
}

// ---------------------------------------------------------------------------
extern "C" void kernel_launch(void* const* d_in, const int* in_sizes, int n_in,
                              void* d_out, int out_size)
{
    const float* x   = (const float*)d_in[0];
    const float* rm  = (const float*)d_in[1];
    const float* W1  = (const float*)d_in[2];
    const float* b1  = (const float*)d_in[3];
    const float* W2  = (const float*)d_in[4];
    float* out = (float*)d_out;

    int B = in_sizes[0] >> 22;

    nca_prep<<<1, 256>>>(W1, W2);
    nca_pass1<<<B << 11, 128, SMEM_P1>>>(x, rm, b1, out);
    nca_pass2<<<B << 10, 256>>>(out);
}